// round 4
// baseline (speedup 1.0000x reference)
#include <cuda_runtime.h>
#include <cuda_bf16.h>

#define NN 50000
#define EE 800000
#define IC  128
#define OC  64

// ---- scratch (no device allocations allowed) ----
__device__ __align__(16) float g_h[NN * OC];   // projected features
__device__ float g_adst[NN];                   // dot(h[n], att[0:64])    (x_i / dst part)
__device__ float g_asrc[NN];                   // dot(h[n], att[64:128])  (x_j / src part)
__device__ int   g_src[EE];                    // normalized edge sources
__device__ int   g_dst[EE];                    // normalized edge dests
__device__ int   g_deg[NN];                    // in-degree (real edges only)
__device__ int   g_ptr[NN + 1];                // CSR row pointers (by dst)
__device__ int   g_cursor[NN];                 // fill cursors
__device__ int   g_col[EE];                    // CSR: src node per edge slot
__device__ int   g_blocksum[128];              // scan block totals (98 used)
__device__ int   g_is64;                       // edge dtype flag

// ============================================================
// K0a: sniff edge_index dtype. int64 layout => odd 32-bit words
// are zero (ids < 2^31). int32 layout => odd words are random
// node ids (prob all-zero ~ (2e-5)^6).
// ============================================================
__global__ void k0_detect(const int* __restrict__ ei32) {
    if (threadIdx.x == 0 && blockIdx.x == 0) {
        int z = (ei32[1] == 0) + (ei32[3] == 0) + (ei32[5] == 0) +
                (ei32[7] == 0) + (ei32[9] == 0) + (ei32[11] == 0);
        g_is64 = (z == 6) ? 1 : 0;
    }
}

// K0b: normalize to int32 arrays, clamped (never trap downstream)
__global__ void k0_convert(const int* __restrict__ ei32) {
    int e = blockIdx.x * blockDim.x + threadIdx.x;
    if (e >= EE) return;
    int s, d;
    if (g_is64) {
        s = ei32[2 * e];             // low word of int64
        d = ei32[2 * (EE + e)];
    } else {
        s = ei32[e];
        d = ei32[EE + e];
    }
    s = min(max(s, 0), NN - 1);
    d = min(max(d, 0), NN - 1);
    g_src[e] = s;
    g_dst[e] = d;
}

// ============================================================
// K1: h = x @ W   (50000x128 @ 128x64, fp32)
// ============================================================
__global__ void k1_gemm(const float* __restrict__ x, const float* __restrict__ W) {
    __shared__ float Ws[64][64];
    __shared__ float Xs[64][68];
    const int tid = threadIdx.x;
    const int tx = tid & 15;
    const int ty = tid >> 4;
    const int n0 = blockIdx.x * 64;

    float acc[4][4];
#pragma unroll
    for (int i = 0; i < 4; i++)
#pragma unroll
        for (int j = 0; j < 4; j++) acc[i][j] = 0.f;

    for (int kc = 0; kc < IC; kc += 64) {
        for (int i = tid; i < 64 * 64; i += 256) {
            int k = i >> 6, c = i & 63;
            Ws[k][c] = W[(kc + k) * OC + c];
        }
        for (int i = tid; i < 64 * 64; i += 256) {
            int r = i >> 6, k = i & 63;
            int n = n0 + r;
            Xs[k][r] = (n < NN) ? x[n * IC + kc + k] : 0.f;
        }
        __syncthreads();
#pragma unroll
        for (int k = 0; k < 64; k++) {
            float4 xv = *(const float4*)&Xs[k][ty * 4];
            float4 wv = *(const float4*)&Ws[k][tx * 4];
            float xa[4] = {xv.x, xv.y, xv.z, xv.w};
            float wa[4] = {wv.x, wv.y, wv.z, wv.w};
#pragma unroll
            for (int i = 0; i < 4; i++)
#pragma unroll
                for (int j = 0; j < 4; j++) acc[i][j] += xa[i] * wa[j];
        }
        __syncthreads();
    }
#pragma unroll
    for (int i = 0; i < 4; i++) {
        int n = n0 + ty * 4 + i;
        if (n < NN) {
#pragma unroll
            for (int j = 0; j < 4; j++) g_h[n * OC + tx * 4 + j] = acc[i][j];
        }
    }
}

// ============================================================
// K2: per-node attention dots + zero degree counters. warp/node
// ============================================================
__global__ void k2_dots(const float* __restrict__ att) {
    const int lane = threadIdx.x & 31;
    const int n = blockIdx.x * 8 + (threadIdx.x >> 5);
    if (n >= NN) return;
    float h0 = g_h[n * OC + lane];
    float h1 = g_h[n * OC + 32 + lane];
    float ad = h0 * att[lane] + h1 * att[32 + lane];
    float as = h0 * att[64 + lane] + h1 * att[96 + lane];
#pragma unroll
    for (int o = 16; o > 0; o >>= 1) {
        ad += __shfl_down_sync(0xffffffffu, ad, o);
        as += __shfl_down_sync(0xffffffffu, as, o);
    }
    if (lane == 0) {
        g_adst[n] = ad;
        g_asrc[n] = as;
        g_deg[n] = 0;
    }
}

// ============================================================
// K3: in-degree histogram over real edges
// ============================================================
__global__ void k3_deg() {
    int e = blockIdx.x * blockDim.x + threadIdx.x;
    if (e >= EE) return;
    atomicAdd(&g_deg[g_dst[e]], 1);
}

// ============================================================
// K4a/b/c: exclusive scan of degrees -> g_ptr  (3-level)
// ============================================================
__global__ void k4a_scan_local() {
    __shared__ int wsum[16];
    int n = blockIdx.x * 512 + threadIdx.x;
    int lane = threadIdx.x & 31, wid = threadIdx.x >> 5;
    int v = (n < NN) ? g_deg[n] : 0;
    int s = v;
#pragma unroll
    for (int o = 1; o < 32; o <<= 1) {
        int t = __shfl_up_sync(0xffffffffu, s, o);
        if (lane >= o) s += t;
    }
    if (lane == 31) wsum[wid] = s;
    __syncthreads();
    if (wid == 0) {
        int ws = (lane < 16) ? wsum[lane] : 0;
#pragma unroll
        for (int o = 1; o < 16; o <<= 1) {
            int t = __shfl_up_sync(0xffffffffu, ws, o);
            if (lane >= o) ws += t;
        }
        if (lane < 16) wsum[lane] = ws;
    }
    __syncthreads();
    int excl = s - v + ((wid > 0) ? wsum[wid - 1] : 0);
    if (n < NN) g_ptr[n] = excl;
    if (threadIdx.x == 0) g_blocksum[blockIdx.x] = wsum[15];
}

__global__ void k4b_scan_blocks(int nb) {
    __shared__ int sh[128];
    int t = threadIdx.x;
    int val = (t < nb) ? g_blocksum[t] : 0;
    sh[t] = val;
    __syncthreads();
    for (int o = 1; o < 128; o <<= 1) {
        int add = (t >= o) ? sh[t - o] : 0;
        __syncthreads();
        sh[t] += add;
        __syncthreads();
    }
    if (t < nb) g_blocksum[t] = sh[t] - val;   // exclusive
}

__global__ void k4c_add_offsets() {
    int n = blockIdx.x * blockDim.x + threadIdx.x;
    if (n < NN) {
        int p = g_ptr[n] + g_blocksum[n >> 9];
        g_ptr[n] = p;
        g_cursor[n] = p;
    }
    if (n == 0) g_ptr[NN] = EE;
}

// ============================================================
// K5: fill CSR columns (src ids grouped by dst)
// ============================================================
__global__ void k5_fill() {
    int e = blockIdx.x * blockDim.x + threadIdx.x;
    if (e >= EE) return;
    int pos = atomicAdd(&g_cursor[g_dst[e]], 1);
    g_col[pos] = g_src[e];
}

// ============================================================
// K6: fused gather + softmax-normalize + bias + L2 norm. warp/node
// ============================================================
__global__ void k6_gather(const float* __restrict__ bias, float* __restrict__ out) {
    const int lane = threadIdx.x & 31;
    const int n = blockIdx.x * 8 + (threadIdx.x >> 5);
    if (n >= NN) return;

    const float ad = g_adst[n];

    // self loop (always present)
    float al = ad + g_asrc[n];
    al = (al > 0.f) ? al : 0.2f * al;
    float w = __expf(al);
    float2 hv = *(const float2*)(g_h + n * OC + lane * 2);
    float wsum = w;
    float a0 = w * hv.x, a1 = w * hv.y;

    const int beg = g_ptr[n];
    const int end = g_ptr[n + 1];
    for (int i = beg; i < end; i++) {
        int s = g_col[i];
        float a = ad + g_asrc[s];
        a = (a > 0.f) ? a : 0.2f * a;
        float we = __expf(a);
        float2 h2 = *(const float2*)(g_h + s * OC + lane * 2);
        wsum += we;
        a0 += we * h2.x;
        a1 += we * h2.y;
    }

    float inv_s = 1.0f / (wsum + 1e-16f);
    float v0 = a0 * inv_s + bias[lane * 2];
    float v1 = a1 * inv_s + bias[lane * 2 + 1];

    float ss = v0 * v0 + v1 * v1;
#pragma unroll
    for (int o = 16; o > 0; o >>= 1) ss += __shfl_xor_sync(0xffffffffu, ss, o);
    float inv = 1.0f / fmaxf(sqrtf(ss), 1e-12f);
    float2 ov = make_float2(v0 * inv, v1 * inv);
    *(float2*)(out + n * OC + lane * 2) = ov;
}

extern "C" void kernel_launch(void* const* d_in, const int* in_sizes, int n_in,
                              void* d_out, int out_size) {
    const float* x = (const float*)d_in[0];
    const int* ei32 = (const int*)d_in[1];   // dtype sniffed on device
    const float* W = (const float*)d_in[2];
    const float* att = (const float*)d_in[3];
    const float* bias = (const float*)d_in[4];
    float* out = (float*)d_out;

    const int nb = (NN + 511) / 512;   // 98 scan blocks

    k0_detect<<<1, 32>>>(ei32);
    k0_convert<<<(EE + 255) / 256, 256>>>(ei32);
    k1_gemm<<<(NN + 63) / 64, 256>>>(x, W);
    k2_dots<<<(NN + 7) / 8, 256>>>(att);
    k3_deg<<<(EE + 255) / 256, 256>>>();
    k4a_scan_local<<<nb, 512>>>();
    k4b_scan_blocks<<<1, 128>>>(nb);
    k4c_add_offsets<<<(NN + 255) / 256, 256>>>();
    k5_fill<<<(EE + 255) / 256, 256>>>();
    k6_gather<<<(NN + 7) / 8, 256>>>(bias, out);
}

// round 6
// speedup vs baseline: 1.0561x; 1.0561x over previous
#include <cuda_runtime.h>
#include <cuda_bf16.h>

#define NN 50000
#define EE 800000
#define IC  128
#define OC  64

// ---- scratch (no device allocations allowed) ----
__device__ __align__(16) float g_h[NN * OC];   // projected features
__device__ float g_adst[NN];                   // dot(h[n], att[0:64])    (x_i / dst part)
__device__ float g_asrc[NN];                   // dot(h[n], att[64:128])  (x_j / src part)
__device__ int   g_src[EE];                    // normalized edge sources
__device__ int   g_dst[EE];                    // normalized edge dests
__device__ int   g_deg[NN];                    // in-degree (real edges only)
__device__ int   g_ptr[NN + 1];                // CSR row pointers (by dst)
__device__ int   g_cursor[NN];                 // fill cursors
__device__ int   g_col[EE];                    // CSR: src node per edge slot
__device__ int   g_blocksum[128];              // scan block totals (98 used)

// ============================================================
// K0: dtype sniff (per-thread, broadcast words) + normalize edge
// indices to int32, clamped. Also zeroes g_deg.
// int64 layout => odd 32-bit words all zero (ids < 2^31).
// ============================================================
__global__ void k0_convert(const int* __restrict__ ei32) {
    int e = blockIdx.x * blockDim.x + threadIdx.x;
    if (e >= EE) return;
    int z = (ei32[1] == 0) + (ei32[3] == 0) + (ei32[5] == 0) +
            (ei32[7] == 0) + (ei32[9] == 0) + (ei32[11] == 0);
    bool is64 = (z == 6);
    int s, d;
    if (is64) {
        s = ei32[2 * e];             // low word of int64
        d = ei32[2 * (EE + e)];
    } else {
        s = ei32[e];
        d = ei32[EE + e];
    }
    s = min(max(s, 0), NN - 1);
    d = min(max(d, 0), NN - 1);
    g_src[e] = s;
    g_dst[e] = d;
    if (e < NN) g_deg[e] = 0;
}

// ============================================================
// K1: h = x @ W (50000x128 @ 128x64 fp32) + fused attention dots
// 64 nodes/block, 256 threads, 4x4 register tile per thread.
// ============================================================
__global__ void k1_gemm(const float* __restrict__ x, const float* __restrict__ W,
                        const float* __restrict__ att) {
    __shared__ float Ws[64][64];
    __shared__ float Xs[64][68];
    const int tid = threadIdx.x;
    const int tx = tid & 15;       // col group: cols tx*4 .. tx*4+3
    const int ty = tid >> 4;       // node group: rows ty*4 .. ty*4+3
    const int n0 = blockIdx.x * 64;

    // att slices for this thread's 4 columns
    float att_d[4], att_s[4];
#pragma unroll
    for (int j = 0; j < 4; j++) {
        att_d[j] = att[tx * 4 + j];
        att_s[j] = att[64 + tx * 4 + j];
    }

    float acc[4][4];
#pragma unroll
    for (int i = 0; i < 4; i++)
#pragma unroll
        for (int j = 0; j < 4; j++) acc[i][j] = 0.f;

    for (int kc = 0; kc < IC; kc += 64) {
        for (int i = tid; i < 64 * 64; i += 256) {
            int k = i >> 6, c = i & 63;
            Ws[k][c] = W[(kc + k) * OC + c];
        }
        for (int i = tid; i < 64 * 64; i += 256) {
            int r = i >> 6, k = i & 63;
            int n = n0 + r;
            Xs[k][r] = (n < NN) ? x[n * IC + kc + k] : 0.f;
        }
        __syncthreads();
#pragma unroll
        for (int k = 0; k < 64; k++) {
            float4 xv = *(const float4*)&Xs[k][ty * 4];
            float4 wv = *(const float4*)&Ws[k][tx * 4];
            float xa[4] = {xv.x, xv.y, xv.z, xv.w};
            float wa[4] = {wv.x, wv.y, wv.z, wv.w};
#pragma unroll
            for (int i = 0; i < 4; i++)
#pragma unroll
                for (int j = 0; j < 4; j++) acc[i][j] += xa[i] * wa[j];
        }
        __syncthreads();
    }

#pragma unroll
    for (int i = 0; i < 4; i++) {
        int n = n0 + ty * 4 + i;
        // store h row chunk
        if (n < NN) {
            float4 v = make_float4(acc[i][0], acc[i][1], acc[i][2], acc[i][3]);
            *(float4*)(g_h + n * OC + tx * 4) = v;
        }
        // fused attention dots: reduce partials across the 16 tx lanes
        float pd = acc[i][0] * att_d[0] + acc[i][1] * att_d[1] +
                   acc[i][2] * att_d[2] + acc[i][3] * att_d[3];
        float ps = acc[i][0] * att_s[0] + acc[i][1] * att_s[1] +
                   acc[i][2] * att_s[2] + acc[i][3] * att_s[3];
#pragma unroll
        for (int o = 8; o > 0; o >>= 1) {
            pd += __shfl_down_sync(0xffffffffu, pd, o, 16);
            ps += __shfl_down_sync(0xffffffffu, ps, o, 16);
        }
        if (tx == 0 && n < NN) {
            g_adst[n] = pd;
            g_asrc[n] = ps;
        }
    }
}

// ============================================================
// K3: in-degree histogram over real edges
// ============================================================
__global__ void k3_deg() {
    int e = blockIdx.x * blockDim.x + threadIdx.x;
    if (e >= EE) return;
    atomicAdd(&g_deg[g_dst[e]], 1);
}

// ============================================================
// K4a/b/c: exclusive scan of degrees -> g_ptr  (3-level)
// ============================================================
__global__ void k4a_scan_local() {
    __shared__ int wsum[16];
    int n = blockIdx.x * 512 + threadIdx.x;
    int lane = threadIdx.x & 31, wid = threadIdx.x >> 5;
    int v = (n < NN) ? g_deg[n] : 0;
    int s = v;
#pragma unroll
    for (int o = 1; o < 32; o <<= 1) {
        int t = __shfl_up_sync(0xffffffffu, s, o);
        if (lane >= o) s += t;
    }
    if (lane == 31) wsum[wid] = s;
    __syncthreads();
    if (wid == 0) {
        int ws = (lane < 16) ? wsum[lane] : 0;
#pragma unroll
        for (int o = 1; o < 16; o <<= 1) {
            int t = __shfl_up_sync(0xffffffffu, ws, o);
            if (lane >= o) ws += t;
        }
        if (lane < 16) wsum[lane] = ws;
    }
    __syncthreads();
    int excl = s - v + ((wid > 0) ? wsum[wid - 1] : 0);
    if (n < NN) g_ptr[n] = excl;
    if (threadIdx.x == 0) g_blocksum[blockIdx.x] = wsum[15];
}

__global__ void k4b_scan_blocks(int nb) {
    __shared__ int sh[128];
    int t = threadIdx.x;
    int val = (t < nb) ? g_blocksum[t] : 0;
    sh[t] = val;
    __syncthreads();
    for (int o = 1; o < 128; o <<= 1) {
        int add = (t >= o) ? sh[t - o] : 0;
        __syncthreads();
        sh[t] += add;
        __syncthreads();
    }
    if (t < nb) g_blocksum[t] = sh[t] - val;   // exclusive
}

__global__ void k4c_add_offsets() {
    int n = blockIdx.x * blockDim.x + threadIdx.x;
    if (n < NN) {
        int p = g_ptr[n] + g_blocksum[n >> 9];
        g_ptr[n] = p;
        g_cursor[n] = p;
    }
    if (n == 0) g_ptr[NN] = EE;
}

// ============================================================
// K5: fill CSR columns (src ids grouped by dst)
// ============================================================
__global__ void k5_fill() {
    int e = blockIdx.x * blockDim.x + threadIdx.x;
    if (e >= EE) return;
    int pos = atomicAdd(&g_cursor[g_dst[e]], 1);
    g_col[pos] = g_src[e];
}

// ============================================================
// K6: fused gather + softmax-normalize + bias + L2 norm. warp/node
// unroll x2 with split accumulators for MLP.
// ============================================================
__global__ void k6_gather(const float* __restrict__ bias, float* __restrict__ out) {
    const int lane = threadIdx.x & 31;
    const int n = blockIdx.x * 8 + (threadIdx.x >> 5);
    if (n >= NN) return;

    const float ad = g_adst[n];

    // self loop (always present)
    float al = ad + g_asrc[n];
    al = (al > 0.f) ? al : 0.2f * al;
    float w = __expf(al);
    float2 hv = *(const float2*)(g_h + n * OC + lane * 2);
    float wsum = w, a0 = w * hv.x, a1 = w * hv.y;
    float wsumB = 0.f, b0 = 0.f, b1 = 0.f;

    const int beg = g_ptr[n];
    const int end = g_ptr[n + 1];
    int i = beg;
    for (; i + 1 < end; i += 2) {
        int s0 = g_col[i];
        int s1 = g_col[i + 1];
        float x0 = g_asrc[s0];
        float x1 = g_asrc[s1];
        float2 h0 = *(const float2*)(g_h + s0 * OC + lane * 2);
        float2 h1 = *(const float2*)(g_h + s1 * OC + lane * 2);
        float aa0 = ad + x0; aa0 = (aa0 > 0.f) ? aa0 : 0.2f * aa0;
        float aa1 = ad + x1; aa1 = (aa1 > 0.f) ? aa1 : 0.2f * aa1;
        float w0 = __expf(aa0);
        float w1 = __expf(aa1);
        wsum  += w0; a0 += w0 * h0.x; a1 += w0 * h0.y;
        wsumB += w1; b0 += w1 * h1.x; b1 += w1 * h1.y;
    }
    if (i < end) {
        int s = g_col[i];
        float a = ad + g_asrc[s];
        a = (a > 0.f) ? a : 0.2f * a;
        float we = __expf(a);
        float2 h2 = *(const float2*)(g_h + s * OC + lane * 2);
        wsum += we; a0 += we * h2.x; a1 += we * h2.y;
    }
    wsum += wsumB; a0 += b0; a1 += b1;

    float inv_s = 1.0f / (wsum + 1e-16f);
    float v0 = a0 * inv_s + bias[lane * 2];
    float v1 = a1 * inv_s + bias[lane * 2 + 1];

    float ss = v0 * v0 + v1 * v1;
#pragma unroll
    for (int o = 16; o > 0; o >>= 1) ss += __shfl_xor_sync(0xffffffffu, ss, o);
    float inv = 1.0f / fmaxf(sqrtf(ss), 1e-12f);
    *(float2*)(out + n * OC + lane * 2) = make_float2(v0 * inv, v1 * inv);
}

extern "C" void kernel_launch(void* const* d_in, const int* in_sizes, int n_in,
                              void* d_out, int out_size) {
    const float* x = (const float*)d_in[0];
    const int* ei32 = (const int*)d_in[1];   // dtype sniffed on device
    const float* W = (const float*)d_in[2];
    const float* att = (const float*)d_in[3];
    const float* bias = (const float*)d_in[4];
    float* out = (float*)d_out;

    const int nb = (NN + 511) / 512;   // 98 scan blocks

    k0_convert<<<(EE + 255) / 256, 256>>>(ei32);
    k1_gemm<<<(NN + 63) / 64, 256>>>(x, W, att);
    k3_deg<<<(EE + 255) / 256, 256>>>();
    k4a_scan_local<<<nb, 512>>>();
    k4b_scan_blocks<<<1, 128>>>(nb);
    k4c_add_offsets<<<(NN + 255) / 256, 256>>>();
    k5_fill<<<(EE + 255) / 256, 256>>>();
    k6_gather<<<(NN + 7) / 8, 256>>>(bias, out);
}